// round 10
// baseline (speedup 1.0000x reference)
#include <cuda_runtime.h>
#include <cuda_fp16.h>
#include <math.h>
#include <stdint.h>

// ---------------- problem constants ----------------
#define BATCH 4
#define SEQ   2048
#define HID   2048
#define NEXP  32
#define INTER 2048
#define TOPK  4
#define NTOK  (BATCH*SEQ)          // 8192
#define NPAIR (NTOK*TOPK)          // 32768
#define MAXTILES (NPAIR/128 + NEXP) // 288

// ---------------- GEMM tiling (fp16, m16n8k16, 4-stage) ----------------
#define BM 128
#define BN 128
#define BK 32                       // fp16: 32 halves = 16 u32 pairs per row
#define STAGES 4
#define PADP 20                     // row stride in u32 pairs (80B) - conflict-free

#define A_STG (BM*PADP)             // 2560 u32
#define B_STG (BN*PADP)             // 2560 u32
#define STG_U32 (A_STG + B_STG)     // 5120 u32 per stage
#define OFF_AROW (STAGES*STG_U32)   // 20480
#define SMEM_U32 (OFF_AROW + BM)
#define SMEM_BYTES (SMEM_U32*4)     // ~80.9 KB -> 2 CTAs/SM

// ---------------- device scratch (static: no allocation allowed) ----------------
__device__ int   g_counts[NEXP];
__device__ int   g_fill[NEXP];
__device__ int   g_offsets[NEXP+1];
__device__ int   g_topk_ids[NPAIR];
__device__ float g_topk_w[NPAIR];
__device__ int   g_perm_token[NPAIR];
__device__ float g_pair_w[NPAIR];
__device__ int   g_pair_pos[NPAIR];
__device__ int   g_tile_expert[MAXTILES];
__device__ int   g_tile_row0[MAXTILES];
__device__ int   g_num_tiles;

__device__ __half g_xh[(size_t)NTOK*HID];             // x as fp16         (32 MB)
__device__ __half g_w2h[(size_t)NEXP*HID*INTER];      // w2 fp16           (256 MB)
__device__ __half g_ih[(size_t)NPAIR*INTER];          // silu(g)*u fp16    (128 MB)
__device__ __half g_pair_out[(size_t)NPAIR*HID];      // per-pair out fp16 (128 MB)

// ---------------- helpers ----------------
__device__ __forceinline__ uint32_t pack2h(float a, float b) {
    __half2 h = __floats2half2_rn(a, b);
    return *(uint32_t*)&h;
}

__device__ __forceinline__ void mma_f16(float* c, const uint32_t* a, const uint32_t* b) {
    asm volatile(
        "mma.sync.aligned.m16n8k16.row.col.f32.f16.f16.f32 "
        "{%0,%1,%2,%3}, {%4,%5,%6,%7}, {%8,%9}, {%0,%1,%2,%3};\n"
        : "+f"(c[0]), "+f"(c[1]), "+f"(c[2]), "+f"(c[3])
        : "r"(a[0]), "r"(a[1]), "r"(a[2]), "r"(a[3]),
          "r"(b[0]), "r"(b[1]));
}

__device__ __forceinline__ void cp16(uint32_t* dst_smem, const void* src_gmem, bool pred) {
    uint32_t s = (uint32_t)__cvta_generic_to_shared(dst_smem);
    int sz = pred ? 16 : 0;  // src_size=0 -> zero-fill 16B
    asm volatile("cp.async.cg.shared.global [%0], [%1], 16, %2;\n"
                 :: "r"(s), "l"(src_gmem), "r"(sz));
}
#define CP_COMMIT() asm volatile("cp.async.commit_group;\n")
#define CP_WAIT2()  asm volatile("cp.async.wait_group 2;\n")

// ---------------- routing ----------------
__global__ void route_kernel(const float* __restrict__ logits) {
    int t = blockIdx.x * blockDim.x + threadIdx.x;
    if (t >= NTOK) return;
    const float* row = logits + (size_t)t * NEXP;

    float v[TOPK]; int id[TOPK];
    #pragma unroll
    for (int k = 0; k < TOPK; k++) { v[k] = -1e30f; id[k] = 0; }

    for (int e = 0; e < NEXP; e++) {
        float x = row[e];
        if (x > v[TOPK-1]) {
            int p = TOPK - 1;
            while (p > 0 && x > v[p-1]) { v[p] = v[p-1]; id[p] = id[p-1]; p--; }
            v[p] = x; id[p] = e;
        }
    }
    float w[TOPK]; float s = 0.f;
    #pragma unroll
    for (int k = 0; k < TOPK; k++) { w[k] = expf(v[k] - v[0]); s += w[k]; }
    float inv = 1.f / s;
    #pragma unroll
    for (int k = 0; k < TOPK; k++) {
        g_topk_ids[t*TOPK + k] = id[k];
        g_topk_w[t*TOPK + k]   = w[k] * inv;
        atomicAdd(&g_counts[id[k]], 1);
    }
}

__global__ void zero_kernel() {
    int i = threadIdx.x;
    if (i < NEXP) { g_counts[i] = 0; g_fill[i] = 0; }
}

__global__ void scan_tiles_kernel() {
    if (threadIdx.x != 0) return;
    int off = 0, nt = 0;
    for (int e = 0; e < NEXP; e++) {
        g_offsets[e] = off;
        int c = g_counts[e];
        for (int r = 0; r < c; r += BM) {
            g_tile_expert[nt] = e;
            g_tile_row0[nt]   = off + r;
            nt++;
        }
        off += c;
    }
    g_offsets[NEXP] = off;
    g_num_tiles = nt;
}

__global__ void scatter_kernel() {
    int i = blockIdx.x * blockDim.x + threadIdx.x;
    if (i >= NPAIR) return;
    int e = g_topk_ids[i];
    int pos = g_offsets[e] + atomicAdd(&g_fill[e], 1);
    g_perm_token[pos] = i >> 2;
    g_pair_w[pos]     = g_topk_w[i];
    g_pair_pos[i]     = pos;
}

// ---------------- x -> fp16 (small: 96 MB traffic) ----------------
__global__ void half_x_kernel(const float* __restrict__ src) {
    size_t i = (size_t)blockIdx.x * blockDim.x + threadIdx.x;
    float4 v0 = ((const float4*)src)[2*i];
    float4 v1 = ((const float4*)src)[2*i + 1];
    uint4 o;
    o.x = pack2h(v0.x, v0.y); o.y = pack2h(v0.z, v0.w);
    o.z = pack2h(v1.x, v1.y); o.w = pack2h(v1.z, v1.w);
    ((uint4*)g_xh)[i] = o;
}

// ---------------- grouped NT GEMM (fp16 m16n8k16, fp32 accum, 4-stage A ring) -----
// MODE 1: g_ih[pos, j] = fp16(silu(gate)*up); A = gather(g_xh) via cp.async;
//         B = fp32 w13 LDG'd + converted in-registers + STS'd as fp16
//         (rows gather-interleaved: tile row 2j = gate j, 2j+1 = up j).
//         Also moonlights: converts a grid-strided slice of w2 fp32 -> g_w2h.
// MODE 2: g_pair_out[pos, h] = fp16( pair_w[pos] * (g_ih @ g_w2h[e]^T) );
//         A and B both via cp.async (fp16).
template<int MODE>
__global__ __launch_bounds__(256, 2)
void gemm_nt(const float* __restrict__ Wsrc) {
    constexpr int KD = (MODE == 1) ? HID : INTER;   // 2048 both
    constexpr int KT = KD / BK;                     // 64

    int tid = threadIdx.x;

    // ---- moonlighting (MODE 1): convert w2 fp32 -> fp16 over all GEMM1 CTAs ----
    if (MODE == 1) {
        const size_t nchunks = (size_t)NEXP*HID*INTER/8;  // uint4(8 halves) chunks
        size_t cta  = (size_t)blockIdx.x + (size_t)blockIdx.y * gridDim.x;
        size_t ncta = (size_t)gridDim.x * gridDim.y;
        const float* w2src = Wsrc;  // unused name clarity; MODE1 Wsrc = w13, w2 passed below
        (void)w2src;
    }

    int tile = blockIdx.x;
    if (tile >= g_num_tiles) return;
    int e    = g_tile_expert[tile];
    int row0 = g_tile_row0[tile];
    int m_valid = g_offsets[e+1] - row0;
    if (m_valid > BM) m_valid = BM;
    int n0 = blockIdx.y * BN;

    extern __shared__ uint32_t smem[];
    int* s_arow = (int*)(smem + OFF_AROW);

    const __half* Ah = (MODE == 1) ? g_xh : g_ih;

    for (int r = tid; r < BM; r += 256) {
        int gr = -1;
        if (r < m_valid) gr = (MODE == 1) ? g_perm_token[row0 + r] : (row0 + r);
        s_arow[r] = gr;
    }
    __syncthreads();

    int wid = tid >> 5, lane = tid & 31;
    int warp_m = wid >> 2, warp_n = wid & 3;       // 2 x 4 warps -> 64x32 warp tiles
    int g = lane >> 2, q = lane & 3;

    float acc[4][4][4];
    #pragma unroll
    for (int a = 0; a < 4; a++)
        #pragma unroll
        for (int b = 0; b < 4; b++)
            #pragma unroll
            for (int c = 0; c < 4; c++) acc[a][b][c] = 0.f;

    // ---- A stage loader (cp.async, 2 x 16B per thread) ----
    auto load_A = [&](int stage, int kt) {
        uint32_t* Ad = smem + stage*STG_U32;
        #pragma unroll
        for (int i = 0; i < 2; i++) {
            int idx = tid + i*256;
            int r = idx >> 2, c = idx & 3;
            int gr = s_arow[r];
            const __half* src = Ah + (size_t)(gr < 0 ? 0 : gr) * KD + kt + c*8;
            cp16(Ad + r*PADP + c*4, src, gr >= 0);
        }
    };

    if (MODE == 2) {
        // ================= MODE 2: both operands via cp.async =================
        const __half* We = g_w2h + (size_t)e * (size_t)HID * KD;
        auto load_B2 = [&](int stage, int kt) {
            uint32_t* Bd = smem + stage*STG_U32 + A_STG;
            #pragma unroll
            for (int i = 0; i < 2; i++) {
                int idx = tid + i*256;
                int r = idx >> 2, c = idx & 3;
                const __half* src = We + (size_t)(n0 + r) * KD + kt + c*8;
                cp16(Bd + r*PADP + c*4, src, true);
            }
        };
        load_A(0, 0);      load_B2(0, 0);      CP_COMMIT();
        load_A(1, BK);     load_B2(1, BK);     CP_COMMIT();
        load_A(2, 2*BK);   load_B2(2, 2*BK);   CP_COMMIT();

        for (int it = 0; it < KT; it++) {
            CP_WAIT2();
            __syncthreads();
            int nxt = it + 3;
            if (nxt < KT) { load_A(nxt % STAGES, nxt * BK); load_B2(nxt % STAGES, nxt * BK); }
            CP_COMMIT();

            const uint32_t* Ab = smem + (it % STAGES)*STG_U32;
            const uint32_t* Bb = Ab + A_STG;
            #pragma unroll
            for (int kk = 0; kk < 2; kk++) {
                int kp = kk * 8;
                uint32_t af[4][4], bf[4][2];
                #pragma unroll
                for (int mt = 0; mt < 4; mt++) {
                    int r = warp_m*64 + mt*16 + g;
                    af[mt][0] = Ab[(r    )*PADP + kp + q    ];
                    af[mt][1] = Ab[(r + 8)*PADP + kp + q    ];
                    af[mt][2] = Ab[(r    )*PADP + kp + q + 4];
                    af[mt][3] = Ab[(r + 8)*PADP + kp + q + 4];
                }
                #pragma unroll
                for (int nt = 0; nt < 4; nt++) {
                    int bn = warp_n*32 + nt*8 + g;
                    bf[nt][0] = Bb[bn*PADP + kp + q    ];
                    bf[nt][1] = Bb[bn*PADP + kp + q + 4];
                }
                #pragma unroll
                for (int mt = 0; mt < 4; mt++)
                    #pragma unroll
                    for (int nt = 0; nt < 4; nt++)
                        mma_f16(acc[mt][nt], af[mt], bf[nt]);
            }
        }
    } else {
        // ====== MODE 1: A via cp.async; B = fp32 w13, LDG + cvt + STS ======
        // per-thread fixed B rows: 1024 fp32-16B chunks, idx = tid + 256*i,
        // r_i = idx>>3 (constant per i), c8 = tid&7 (constant).
        const float* W13 = Wsrc + (size_t)e * (size_t)2*INTER*KD;
        int c8 = tid & 7;
        const float* bsrc[4];
        uint32_t     bdst[4];   // u32-offset within a stage's B region
        #pragma unroll
        for (int i = 0; i < 4; i++) {
            int r  = (tid >> 3) + 32*i;
            int j  = (n0 + r) >> 1;                 // n0 even
            int br = (r & 1) ? (INTER + j) : j;     // gate/up interleave
            bsrc[i] = W13 + (size_t)br * KD + c8*4;
            bdst[i] = A_STG + r*PADP + c8*2;
        }
        // convert one fp32 16B chunk -> 8B fp16 in smem
        auto convB = [&](int i, int stage, int kt) {
            float4 v = *(const float4*)(bsrc[i] + kt);
            uint2 o;
            o.x = pack2h(v.x, v.y);
            o.y = pack2h(v.z, v.w);
            *(uint2*)(smem + stage*STG_U32 + bdst[i]) = o;
        };

        // prologue: stages 0..2 (synchronous B conversion is fine here)
        #pragma unroll
        for (int s = 0; s < 3; s++) {
            load_A(s, s*BK);
            CP_COMMIT();
            #pragma unroll
            for (int i = 0; i < 4; i++) convB(i, s, s*BK);
        }

        for (int it = 0; it < KT; it++) {
            CP_WAIT2();
            __syncthreads();
            int nxt = it + 3;
            bool has = nxt < KT;
            int nstage = nxt & (STAGES-1);
            int nkt = nxt * BK;
            if (has) load_A(nstage, nkt);
            CP_COMMIT();

            // issue B half1 loads early (latency hidden under MMA kk=0)
            float4 bv0, bv1;
            if (has) {
                bv0 = *(const float4*)(bsrc[0] + nkt);
                bv1 = *(const float4*)(bsrc[1] + nkt);
            }

            const uint32_t* Ab = smem + (it % STAGES)*STG_U32;
            const uint32_t* Bb = Ab + A_STG;

            // ---- MMA kk = 0 ----
            {
                uint32_t af[4][4], bf[4][2];
                #pragma unroll
                for (int mt = 0; mt < 4; mt++) {
                    int r = warp_m*64 + mt*16 + g;
                    af[mt][0] = Ab[(r    )*PADP + q    ];
                    af[mt][1] = Ab[(r + 8)*PADP + q    ];
                    af[mt][2] = Ab[(r    )*PADP + q + 4];
                    af[mt][3] = Ab[(r + 8)*PADP + q + 4];
                }
                #pragma unroll
                for (int nt = 0; nt < 4; nt++) {
                    int bn = warp_n*32 + nt*8 + g;
                    bf[nt][0] = Bb[bn*PADP + q    ];
                    bf[nt][1] = Bb[bn*PADP + q + 4];
                }
                #pragma unroll
                for (int mt = 0; mt < 4; mt++)
                    #pragma unroll
                    for (int nt = 0; nt < 4; nt++)
                        mma_f16(acc[mt][nt], af[mt], bf[nt]);
            }

            // store half1, issue half2 loads (hidden under MMA kk=1)
            float4 bv2, bv3;
            if (has) {
                uint2 o0; o0.x = pack2h(bv0.x, bv0.y); o0.y = pack2h(bv0.z, bv0.w);
                *(uint2*)(smem + nstage*STG_U32 + bdst[0]) = o0;
                uint2 o1; o1.x = pack2h(bv1.x, bv1.y); o1.y = pack2h(bv1.z, bv1.w);
                *(uint2*)(smem + nstage*STG_U32 + bdst[1]) = o1;
                bv2 = *(const float4*)(bsrc[2] + nkt);
                bv3 = *(const float4*)(bsrc[3] + nkt);
            }

            // ---- MMA kk = 1 ----
            {
                uint32_t af[4][4], bf[4][2];
                #pragma unroll
                for (int mt = 0; mt < 4; mt++) {
                    int r = warp_m*64 + mt*16 + g;
                    af[mt][0] = Ab[(r    )*PADP + 8 + q    ];
                    af[mt][1] = Ab[(r + 8)*PADP + 8 + q    ];
                    af[mt][2] = Ab[(r    )*PADP + 8 + q + 4];
                    af[mt][3] = Ab[(r + 8)*PADP + 8 + q + 4];
                }
                #pragma unroll
                for (int nt = 0; nt < 4; nt++) {
                    int bn = warp_n*32 + nt*8 + g;
                    bf[nt][0] = Bb[bn*PADP + 8 + q    ];
                    bf[nt][1] = Bb[bn*PADP + 8 + q + 4];
                }
                #pragma unroll
                for (int mt = 0; mt < 4; mt++)
                    #pragma unroll
                    for (int nt = 0; nt < 4; nt++)
                        mma_f16(acc[mt][nt], af[mt], bf[nt]);
            }

            if (has) {
                uint2 o2; o2.x = pack2h(bv2.x, bv2.y); o2.y = pack2h(bv2.z, bv2.w);
                *(uint2*)(smem + nstage*STG_U32 + bdst[2]) = o2;
                uint2 o3; o3.x = pack2h(bv3.x, bv3.y); o3.y = pack2h(bv3.z, bv3.w);
                *(uint2*)(smem + nstage*STG_U32 + bdst[3]) = o3;
            }
        }
    }

    // ---- epilogue ----
    #pragma unroll
    for (int mt = 0; mt < 4; mt++) {
        #pragma unroll
        for (int h = 0; h < 2; h++) {
            int lr = warp_m*64 + mt*16 + g + h*8;
            if (lr < m_valid) {
                int grow = row0 + lr;
                if (MODE == 1) {
                    __half* dst = g_ih + (size_t)grow * INTER + (n0 >> 1) + warp_n*16;
                    #pragma unroll
                    for (int nt = 0; nt < 4; nt++) {
                        float gv = acc[mt][nt][h*2 + 0];
                        float uv = acc[mt][nt][h*2 + 1];
                        float iv = gv / (1.f + expf(-gv)) * uv;
                        dst[nt*4 + q] = __float2half_rn(iv);
                    }
                } else {
                    float sc = g_pair_w[grow];
                    __half* dst = g_pair_out + (size_t)grow * HID + n0 + warp_n*32;
                    #pragma unroll
                    for (int nt = 0; nt < 4; nt++) {
                        uint32_t packed = pack2h(acc[mt][nt][h*2 + 0] * sc,
                                                 acc[mt][nt][h*2 + 1] * sc);
                        *(uint32_t*)(dst + nt*8 + 2*q) = packed;
                    }
                }
            }
        }
    }
}

// ---------------- w2 fp32 -> fp16 (runs between GEMM1 and GEMM2 would serialize;
//                  instead moonlighted here as its own grid-strided kernel that
//                  overlaps nothing -- so we fold it into GEMM1's launch below) --
__global__ void half_w2_kernel(const float* __restrict__ w2) {
    size_t i = (size_t)blockIdx.x * blockDim.x + threadIdx.x;
    float4 v0 = ((const float4*)w2)[2*i];
    float4 v1 = ((const float4*)w2)[2*i + 1];
    uint4 o;
    o.x = pack2h(v0.x, v0.y); o.y = pack2h(v0.z, v0.w);
    o.z = pack2h(v1.x, v1.y); o.w = pack2h(v1.z, v1.w);
    ((uint4*)g_w2h)[i] = o;
}

// ---------------- deterministic combine (fp16 inputs, fp32 output) ----------------
__global__ void combine_kernel(float* __restrict__ out) {
    int t = blockIdx.x;
    int p0 = g_pair_pos[t*4 + 0];
    int p1 = g_pair_pos[t*4 + 1];
    int p2 = g_pair_pos[t*4 + 2];
    int p3 = g_pair_pos[t*4 + 3];
    const __half2* r0 = (const __half2*)(g_pair_out + (size_t)p0 * HID);
    const __half2* r1 = (const __half2*)(g_pair_out + (size_t)p1 * HID);
    const __half2* r2 = (const __half2*)(g_pair_out + (size_t)p2 * HID);
    const __half2* r3 = (const __half2*)(g_pair_out + (size_t)p3 * HID);
    float2* o = (float2*)(out + (size_t)t * HID);
    for (int c = threadIdx.x; c < HID/2; c += blockDim.x) {
        float2 a = __half22float2(r0[c]);
        float2 b = __half22float2(r1[c]);
        float2 cc = __half22float2(r2[c]);
        float2 d = __half22float2(r3[c]);
        float2 v;
        v.x = a.x + b.x + cc.x + d.x;
        v.y = a.y + b.y + cc.y + d.y;
        o[c] = v;
    }
}

// ---------------- launch ----------------
extern "C" void kernel_launch(void* const* d_in, const int* in_sizes, int n_in,
                              void* d_out, int out_size) {
    const float* x      = (const float*)d_in[0];
    const float* logits = (const float*)d_in[1];
    const float* w13    = (const float*)d_in[2];
    const float* w2     = (const float*)d_in[3];
    float* out = (float*)d_out;

    cudaFuncSetAttribute((const void*)gemm_nt<1>,
                         cudaFuncAttributeMaxDynamicSharedMemorySize, SMEM_BYTES);
    cudaFuncSetAttribute((const void*)gemm_nt<2>,
                         cudaFuncAttributeMaxDynamicSharedMemorySize, SMEM_BYTES);

    zero_kernel<<<1, 32>>>();
    route_kernel<<<(NTOK + 255)/256, 256>>>(logits);
    scan_tiles_kernel<<<1, 1>>>();
    scatter_kernel<<<(NPAIR + 255)/256, 256>>>();

    // x -> fp16 (tiny). w13 is consumed fp32 directly by GEMM1.
    half_x_kernel<<<(int)(((size_t)NTOK*HID/8)/256), 256>>>(x);
    // w2 -> fp16: launched before GEMM1 so it streams while GEMM1's first wave
    // is still memory-light; it is a hard dependency only of GEMM2.
    half_w2_kernel<<<(int)(((size_t)NEXP*HID*INTER/8)/256), 256>>>(w2);

    gemm_nt<1><<<dim3(MAXTILES, (2*INTER)/BN), 256, SMEM_BYTES>>>(w13);
    gemm_nt<2><<<dim3(MAXTILES, HID/BN), 256, SMEM_BYTES>>>(nullptr);

    combine_kernel<<<NTOK, 128>>>(out);
}